// round 3
// baseline (speedup 1.0000x reference)
#include <cuda_runtime.h>

#define KSZ   5
#define CIN   3
#define BATCH 2
#define HH    48
#define KN    16
#define OH    44
#define PP    1936            // OH*OH
#define IMG_ELEMS (CIN*HH*HH) // 6912

#define TILE   64
#define NTILES ((PP + TILE - 1) / TILE)   // 31

typedef unsigned long long u64;

__device__ __forceinline__ u64 pack2(float lo, float hi) {
    u64 r; asm("mov.b64 %0, {%1,%2};" : "=l"(r) : "f"(lo), "f"(hi)); return r;
}
__device__ __forceinline__ void fma2(u64 &d, u64 a, u64 b) {
    asm("fma.rn.f32x2 %0, %1, %2, %0;" : "+l"(d) : "l"(a), "l"(b));
}
__device__ __forceinline__ float2 unpack2(u64 v) {
    float2 f; asm("mov.b64 {%0,%1}, %2;" : "=f"(f.x), "=f"(f.y) : "l"(v)); return f;
}

// ---------------------------------------------------------------------------
// sigma[b,kn,p,q] = (sum_f xm[b,p,f]*xm[b,q,f]) * softplus(w_sigma[kn])
// 64x64 tile, 256 threads (16x16), 4x4 microtile -> low regs, 4 CTAs/SM.
// Compute layout: p = p0 + ty*4 + r,  q = q0 + tx + 16s (conflict-free LDS).
// Epilogue: one SMEM transpose, then 16 scaled planes via streaming STG.128.
// ---------------------------------------------------------------------------
__global__ __launch_bounds__(256, 4)
void vdp_sigma_kernel(const float* __restrict__ mu_in,
                      const float* __restrict__ w_sigma,
                      float* __restrict__ sigma)
{
    __shared__ float img[IMG_ELEMS];
    __shared__ float spv[KN];
    __shared__ float tile[TILE][TILE + 4];   // 64 x 68 floats

    const int tid = threadIdx.x;
    const int tx  = tid & 15;
    const int ty  = tid >> 4;
    const int b   = blockIdx.z;
    const int p0  = blockIdx.y * TILE;
    const int q0  = blockIdx.x * TILE;

    // Load per-batch image (27.6 KB) + softplus scales
    const float* src = mu_in + b * IMG_ELEMS;
    for (int i = tid; i < IMG_ELEMS; i += 256) img[i] = src[i];
    if (tid < KN) spv[tid] = log1pf(expf(w_sigma[tid]));
    __syncthreads();

    // Patch base addresses (clamped; out-of-range rows masked at store time)
    int basep[4], baseq[4];
    #pragma unroll
    for (int r = 0; r < 4; r++) {
        int p = p0 + ty * 4 + r;
        int pc = (p < PP) ? p : 0;
        int ph = pc / OH, pw = pc - ph * OH;
        basep[r] = ph * HH + pw;
    }
    #pragma unroll
    for (int s = 0; s < 4; s++) {
        int q = q0 + tx + s * 16;
        int qc = (q < PP) ? q : 0;
        int qh = qc / OH, qw = qc - qh * OH;
        baseq[s] = qh * HH + qw;
    }

    u64 acc[4][2];
    #pragma unroll
    for (int r = 0; r < 4; r++) { acc[r][0] = 0ULL; acc[r][1] = 0ULL; }

    // Gram accumulation: 3 channels x 25 unrolled taps
    #pragma unroll 1
    for (int c = 0; c < CIN; c++) {
        int bp[4], bq[4];
        const int coff = c * (HH * HH);
        #pragma unroll
        for (int r = 0; r < 4; r++) bp[r] = basep[r] + coff;
        #pragma unroll
        for (int s = 0; s < 4; s++) bq[s] = baseq[s] + coff;

        #pragma unroll
        for (int i = 0; i < KSZ; i++) {
            #pragma unroll
            for (int j = 0; j < KSZ; j++) {
                const int off = i * HH + j;
                float av[4], bv[4];
                #pragma unroll
                for (int r = 0; r < 4; r++) av[r] = img[bp[r] + off];
                #pragma unroll
                for (int s = 0; s < 4; s++) bv[s] = img[bq[s] + off];

                u64 avp[4], bvp[2];
                #pragma unroll
                for (int r = 0; r < 4; r++) avp[r] = pack2(av[r], av[r]);
                bvp[0] = pack2(bv[0], bv[1]);
                bvp[1] = pack2(bv[2], bv[3]);

                #pragma unroll
                for (int r = 0; r < 4; r++) {
                    fma2(acc[r][0], avp[r], bvp[0]);
                    fma2(acc[r][1], avp[r], bvp[1]);
                }
            }
        }
    }

    // -------- Epilogue: SMEM transpose then vectorized streaming stores -----
    __syncthreads();
    #pragma unroll
    for (int r = 0; r < 4; r++) {
        float2 f0 = unpack2(acc[r][0]);
        float2 f1 = unpack2(acc[r][1]);
        float* row = tile[4 * ty + r];
        row[tx]      = f0.x;
        row[tx + 16] = f0.y;
        row[tx + 32] = f1.x;
        row[tx + 48] = f1.y;
    }
    __syncthreads();

    const int  prow = tid >> 2;            // 0..63
    const int  qoff = (tid & 3) * 16;      // 16 consecutive q per thread
    const int  p    = p0 + prow;

    if (p < PP) {
        float4 v[4];
        #pragma unroll
        for (int k = 0; k < 4; k++)
            v[k] = *(const float4*)&tile[prow][qoff + 4 * k];

        bool qv[4];
        #pragma unroll
        for (int k = 0; k < 4; k++) qv[k] = (q0 + qoff + 4 * k) < PP;

        const size_t planeStride = (size_t)PP * PP;
        float* base = sigma + (size_t)b * KN * planeStride
                            + (size_t)p * PP + (size_t)(q0 + qoff);
        #pragma unroll
        for (int kn = 0; kn < KN; kn++) {
            const float s = spv[kn];
            float* o = base + (size_t)kn * planeStride;
            #pragma unroll
            for (int k = 0; k < 4; k++) {
                if (qv[k]) {
                    float4 w;
                    w.x = v[k].x * s; w.y = v[k].y * s;
                    w.z = v[k].z * s; w.w = v[k].w * s;
                    __stcs((float4*)(o + 4 * k), w);
                }
            }
        }
    }
}

// ---------------------------------------------------------------------------
// Mean path: plain valid conv, one thread per output element.
// ---------------------------------------------------------------------------
__global__ __launch_bounds__(256)
void vdp_mu_kernel(const float* __restrict__ mu_in,
                   const float* __restrict__ w_mu,
                   float* __restrict__ mu_out)
{
    int idx = blockIdx.x * blockDim.x + threadIdx.x;
    const int total = BATCH * KN * OH * OH;
    if (idx >= total) return;

    int ox = idx % OH;
    int oy = (idx / OH) % OH;
    int kn = (idx / (OH * OH)) % KN;
    int b  = idx / (OH * OH * KN);

    const float* im = mu_in + b * IMG_ELEMS;
    const float* w  = w_mu + kn * (CIN * KSZ * KSZ);

    float acc = 0.0f;
    #pragma unroll
    for (int c = 0; c < CIN; c++)
        #pragma unroll
        for (int i = 0; i < KSZ; i++)
            #pragma unroll
            for (int j = 0; j < KSZ; j++)
                acc = fmaf(__ldg(&im[c * HH * HH + (oy + i) * HH + ox + j]),
                           __ldg(&w[c * KSZ * KSZ + i * KSZ + j]), acc);
    mu_out[idx] = acc;
}

extern "C" void kernel_launch(void* const* d_in, const int* in_sizes, int n_in,
                              void* d_out, int out_size)
{
    const float* mu_in   = (const float*)d_in[0];
    const float* w_mu    = (const float*)d_in[1];
    const float* w_sigma = (const float*)d_in[2];

    float* out    = (float*)d_out;
    float* mu_out = out;
    float* sigma  = out + (size_t)BATCH * KN * OH * OH;

    const int mu_total = BATCH * KN * OH * OH;
    vdp_mu_kernel<<<(mu_total + 255) / 256, 256>>>(mu_in, w_mu, mu_out);

    dim3 grid(NTILES, NTILES, BATCH);   // 31 x 31 x 2 = 1922 CTAs
    vdp_sigma_kernel<<<grid, 256>>>(mu_in, w_sigma, sigma);
}

// round 4
// speedup vs baseline: 2.3501x; 2.3501x over previous
#include <cuda_runtime.h>

#define KSZ   5
#define CIN   3
#define BATCH 2
#define HH    48
#define KN    16
#define OH    44
#define PP    1936            // OH*OH
#define IMG_ELEMS (CIN*HH*HH) // 6912

#define TILE 128
#define QV   (PP / 4)         // 484 vec4s per row

typedef unsigned long long u64;

// 30 MB scratch for the unscaled Gram matrix xxT[b, p, q]
__device__ float g_xxT[(size_t)BATCH * PP * PP];

__device__ __forceinline__ u64 pack2(float lo, float hi) {
    u64 r; asm("mov.b64 %0, {%1,%2};" : "=l"(r) : "f"(lo), "f"(hi)); return r;
}
__device__ __forceinline__ void fma2(u64 &d, u64 a, u64 b) {
    asm("fma.rn.f32x2 %0, %1, %2, %0;" : "+l"(d) : "l"(a), "l"(b));
}
__device__ __forceinline__ float2 unpack2(u64 v) {
    float2 f; asm("mov.b64 {%0,%1}, %2;" : "=f"(f.x), "=f"(f.y) : "l"(v)); return f;
}

// ---------------------------------------------------------------------------
// Kernel A: xxT[b,p,q] = sum_f xm[b,p,f] * xm[b,q,f]
// 128x128 tile, 256 threads (16x16), 8x8 microtile, f32x2 accumulation.
// p = p0 + ty*8 + r,  q = q0 + tx + 16s (conflict-free LDS: b-loads stride-1,
// a-loads broadcast). Output is only 30 MB -> light epilogue.
// ---------------------------------------------------------------------------
__global__ __launch_bounds__(256, 2)
void vdp_gram_kernel(const float* __restrict__ mu_in)
{
    __shared__ float img[IMG_ELEMS];

    const int tid = threadIdx.x;
    const int tx  = tid & 15;
    const int ty  = tid >> 4;
    const int b   = blockIdx.z;
    const int p0  = blockIdx.y * TILE;
    const int q0  = blockIdx.x * TILE;

    const float* src = mu_in + b * IMG_ELEMS;
    for (int i = tid; i < IMG_ELEMS; i += 256) img[i] = src[i];
    __syncthreads();

    int basep[8], baseq[8];
    #pragma unroll
    for (int r = 0; r < 8; r++) {
        int p = p0 + ty * 8 + r;
        int pc = (p < PP) ? p : 0;
        int ph = pc / OH, pw = pc - ph * OH;
        basep[r] = ph * HH + pw;
    }
    #pragma unroll
    for (int s = 0; s < 8; s++) {
        int q = q0 + tx + s * 16;
        int qc = (q < PP) ? q : 0;
        int qh = qc / OH, qw = qc - qh * OH;
        baseq[s] = qh * HH + qw;
    }

    u64 acc[8][4];
    #pragma unroll
    for (int r = 0; r < 8; r++)
        #pragma unroll
        for (int h = 0; h < 4; h++) acc[r][h] = 0ULL;

    #pragma unroll 1
    for (int c = 0; c < CIN; c++) {
        int bp[8], bq[8];
        const int coff = c * (HH * HH);
        #pragma unroll
        for (int r = 0; r < 8; r++) bp[r] = basep[r] + coff;
        #pragma unroll
        for (int s = 0; s < 8; s++) bq[s] = baseq[s] + coff;

        #pragma unroll
        for (int i = 0; i < KSZ; i++) {
            #pragma unroll
            for (int j = 0; j < KSZ; j++) {
                const int off = i * HH + j;
                float av[8], bv[8];
                #pragma unroll
                for (int r = 0; r < 8; r++) av[r] = img[bp[r] + off];
                #pragma unroll
                for (int s = 0; s < 8; s++) bv[s] = img[bq[s] + off];

                u64 avp[8], bvp[4];
                #pragma unroll
                for (int r = 0; r < 8; r++) avp[r] = pack2(av[r], av[r]);
                #pragma unroll
                for (int h = 0; h < 4; h++) bvp[h] = pack2(bv[2*h], bv[2*h+1]);

                #pragma unroll
                for (int r = 0; r < 8; r++)
                    #pragma unroll
                    for (int h = 0; h < 4; h++)
                        fma2(acc[r][h], avp[r], bvp[h]);
            }
        }
    }

    // Light epilogue: scalar stores of the unscaled Gram tile (30 MB total)
    float* gbase = g_xxT + (size_t)b * PP * PP;
    #pragma unroll
    for (int r = 0; r < 8; r++) {
        int p = p0 + ty * 8 + r;
        if (p >= PP) continue;
        float* row = gbase + (size_t)p * PP;
        #pragma unroll
        for (int h = 0; h < 4; h++) {
            float2 f = unpack2(acc[r][h]);
            int q1 = q0 + tx + 32 * h;
            int q2 = q1 + 16;
            if (q1 < PP) row[q1] = f.x;
            if (q2 < PP) row[q2] = f.y;
        }
    }
}

// ---------------------------------------------------------------------------
// Kernel B: sigma[b,kn,p,q] = xxT[b,p,q] * softplus(w_sigma[kn])
// Pure streaming broadcast: 1 LDG.128 (L2-resident xxT) -> 16 STG.128.
// Full occupancy; should run at the HBM write wall.
// ---------------------------------------------------------------------------
__global__ __launch_bounds__(256)
void vdp_scale_kernel(const float* __restrict__ w_sigma,
                      float* __restrict__ sigma)
{
    __shared__ float sp[KN];
    if (threadIdx.x < KN) sp[threadIdx.x] = log1pf(expf(w_sigma[threadIdx.x]));
    __syncthreads();

    int idx = blockIdx.x * 256 + threadIdx.x;
    const int total = BATCH * PP * QV;
    if (idx >= total) return;

    int qv = idx % QV;
    int p  = (idx / QV) % PP;
    int b  = idx / (QV * PP);

    const float4 v = *(const float4*)&g_xxT[((size_t)b * PP + p) * PP + qv * 4];

    const size_t planeStride = (size_t)PP * PP;
    float* o = sigma + ((size_t)b * KN) * planeStride + (size_t)p * PP + qv * 4;

    #pragma unroll
    for (int kn = 0; kn < KN; kn++) {
        const float s = sp[kn];
        float4 w;
        w.x = v.x * s; w.y = v.y * s; w.z = v.z * s; w.w = v.w * s;
        __stcs((float4*)o, w);
        o += planeStride;
    }
}

// ---------------------------------------------------------------------------
// Mean path: plain valid conv, one thread per output element.
// ---------------------------------------------------------------------------
__global__ __launch_bounds__(256)
void vdp_mu_kernel(const float* __restrict__ mu_in,
                   const float* __restrict__ w_mu,
                   float* __restrict__ mu_out)
{
    int idx = blockIdx.x * blockDim.x + threadIdx.x;
    const int total = BATCH * KN * OH * OH;
    if (idx >= total) return;

    int ox = idx % OH;
    int oy = (idx / OH) % OH;
    int kn = (idx / (OH * OH)) % KN;
    int b  = idx / (OH * OH * KN);

    const float* im = mu_in + b * IMG_ELEMS;
    const float* w  = w_mu + kn * (CIN * KSZ * KSZ);

    float acc = 0.0f;
    #pragma unroll
    for (int c = 0; c < CIN; c++)
        #pragma unroll
        for (int i = 0; i < KSZ; i++)
            #pragma unroll
            for (int j = 0; j < KSZ; j++)
                acc = fmaf(__ldg(&im[c * HH * HH + (oy + i) * HH + ox + j]),
                           __ldg(&w[c * KSZ * KSZ + i * KSZ + j]), acc);
    mu_out[idx] = acc;
}

extern "C" void kernel_launch(void* const* d_in, const int* in_sizes, int n_in,
                              void* d_out, int out_size)
{
    const float* mu_in   = (const float*)d_in[0];
    const float* w_mu    = (const float*)d_in[1];
    const float* w_sigma = (const float*)d_in[2];

    float* out    = (float*)d_out;
    float* mu_out = out;
    float* sigma  = out + (size_t)BATCH * KN * OH * OH;

    const int mu_total = BATCH * KN * OH * OH;
    vdp_mu_kernel<<<(mu_total + 255) / 256, 256>>>(mu_in, w_mu, mu_out);

    dim3 gridA((PP + TILE - 1) / TILE, (PP + TILE - 1) / TILE, BATCH);  // 16x16x2
    vdp_gram_kernel<<<gridA, 256>>>(mu_in);

    const int totalB = BATCH * PP * QV;                                 // 1.87M
    vdp_scale_kernel<<<(totalB + 255) / 256, 256>>>(w_sigma, sigma);
}